// round 5
// baseline (speedup 1.0000x reference)
#include <cuda_runtime.h>
#include <cuda_bf16.h>
#include <cstdint>

// ===================== problem constants =====================
#define N_TOK 8192
#define DIM   256          // K
#define BT    64           // CTA tile: 64 x 64
#define THREADS 256        // 8 warps: 4(i) x 2(j); warp tile 16(i) x 32(j)
#define NT2   (N_TOK / BT)             // 128
#define NTILES (NT2 * (NT2 + 1) / 2)   // 8256

__device__ __nv_bfloat16 g_emb[N_TOK * DIM];
__device__ float g_x2[N_TOK];

// ===================== helpers =====================
__device__ __forceinline__ uint32_t smem_u32(const void* p) {
    uint32_t a;
    asm("{ .reg .u64 t; cvta.to.shared.u64 t, %1; cvt.u32.u64 %0, t; }" : "=r"(a) : "l"(p));
    return a;
}

#define CP16(dst, src) \
    asm volatile("cp.async.cg.shared.global [%0], [%1], 16;" :: "r"(dst), "l"(src) : "memory")

__device__ __forceinline__ void ldsm4(uint32_t* r, uint32_t addr) {
    asm volatile("ldmatrix.sync.aligned.m8n8.x4.shared.b16 {%0,%1,%2,%3}, [%4];"
        : "=r"(r[0]), "=r"(r[1]), "=r"(r[2]), "=r"(r[3]) : "r"(addr));
}

__device__ __forceinline__ void mma16816(float* c, const uint32_t* a, uint32_t b0, uint32_t b1) {
    asm volatile("mma.sync.aligned.m16n8k16.row.col.f32.bf16.bf16.f32 "
        "{%0,%1,%2,%3}, {%4,%5,%6,%7}, {%8,%9}, {%0,%1,%2,%3};"
        : "+f"(c[0]), "+f"(c[1]), "+f"(c[2]), "+f"(c[3])
        : "r"(a[0]), "r"(a[1]), "r"(a[2]), "r"(a[3]), "r"(b0), "r"(b1));
}

// smem operand layout: row-major 512B rows (256 bf16), 16B chunks XOR-swizzled.
__device__ __forceinline__ uint32_t sw_off(int r, int kc) {
    return (uint32_t)r * 512u + (uint32_t)((kc ^ (r & 7)) << 4);
}

// ===================== prep: fp32 -> bf16 + exact fp32 row norms =====================
__global__ void prep_kernel(const float* __restrict__ emb) {
    const int row  = (blockIdx.x << 3) + (threadIdx.x >> 5);
    const int lane = threadIdx.x & 31;
    const float4* src = (const float4*)(emb + (size_t)row * DIM + lane * 8);
    float4 v0 = src[0], v1 = src[1];
    float s = v0.x * v0.x;
    s = fmaf(v0.y, v0.y, s); s = fmaf(v0.z, v0.z, s); s = fmaf(v0.w, v0.w, s);
    s = fmaf(v1.x, v1.x, s); s = fmaf(v1.y, v1.y, s);
    s = fmaf(v1.z, v1.z, s); s = fmaf(v1.w, v1.w, s);
#pragma unroll
    for (int o = 16; o; o >>= 1) s += __shfl_xor_sync(0xffffffffu, s, o);

    __nv_bfloat162 b0 = __floats2bfloat162_rn(v0.x, v0.y);
    __nv_bfloat162 b1 = __floats2bfloat162_rn(v0.z, v0.w);
    __nv_bfloat162 b2 = __floats2bfloat162_rn(v1.x, v1.y);
    __nv_bfloat162 b3 = __floats2bfloat162_rn(v1.z, v1.w);
    uint4 packed;
    packed.x = *(uint32_t*)&b0; packed.y = *(uint32_t*)&b1;
    packed.z = *(uint32_t*)&b2; packed.w = *(uint32_t*)&b3;
    *(uint4*)(g_emb + (size_t)row * DIM + lane * 8) = packed;
    if (lane == 0) g_x2[row] = s;
}

// ===================== smem layout (per CTA, 66048 B) =====================
// Phase 1: A tile (64 rows) 32KB @0, B tile (64 rows) 32KB @32768
// Phase 2 (overlaps phase-1 region): probs staging 64x69 fl @0 (17664B),
//          dists @17664. Norms beyond: xi2 @65536 (256B), xj2 @65792 (256B).
#define SA   0u
#define SBo  32768u
#define SP   0u
#define SD   17664u
#define SXI  65536u
#define SXJ  65792u
#define SMEM_TOTAL 66048
#define PSTRIDE 69   // odd, coprime with 32 -> conflict-free column LDS

__global__ void __launch_bounds__(THREADS, 3)
poincare_kernel(float* __restrict__ out) {
    extern __shared__ char smem[];
    uint32_t sb = smem_u32(smem);

    const int tid  = threadIdx.x;
    const int lane = tid & 31;
    const int w    = tid >> 5;
    const int wm   = w >> 1;   // warp row (4): 16 i-rows each
    const int wn   = w & 1;    // warp col (2): 32 j-cols each

    // ---- decode upper-triangular tile (ti <= tj) over 128x128 ----
    const int t = blockIdx.x;
    int ti = (int)((257.0f - sqrtf(66049.0f - 8.0f * (float)t)) * 0.5f);
    #define TRIBASE(x) ((x) * NT2 - (x) * ((x) - 1) / 2)
    while (ti > 0 && TRIBASE(ti) > t) ti--;
    while (TRIBASE(ti + 1) <= t) ti++;
    const int tj = ti + (t - TRIBASE(ti));

    const int i0 = ti * BT;
    const int j0 = tj * BT;
    const bool diag = (ti == tj);

    // stage row norms
    if (tid < 64)            ((float*)(smem + SXI))[tid]      = g_x2[i0 + tid];
    else if (tid < 128)      ((float*)(smem + SXJ))[tid - 64] = g_x2[j0 + tid - 64];

    // stage A and B (64 rows each, full K=256): 2048 chunks each
#pragma unroll
    for (int k = 0; k < 8; k++) {
        int id = k * THREADS + tid;
        int r = id >> 5, kc = id & 31;
        CP16(sb + SA  + sw_off(r, kc), &g_emb[(size_t)(i0 + r) * DIM + kc * 8]);
        CP16(sb + SBo + sw_off(r, kc), &g_emb[(size_t)(j0 + r) * DIM + kc * 8]);
    }
    asm volatile("cp.async.commit_group;" ::: "memory");
    asm volatile("cp.async.wait_all;" ::: "memory");
    __syncthreads();

    // ---------------- MMA mainloop: 16 K-steps of k16 ----------------
    float acc[4][4];   // nt x frag
#pragma unroll
    for (int nt = 0; nt < 4; nt++)
#pragma unroll
        for (int e = 0; e < 4; e++) acc[nt][e] = 0.f;

    const int lrow = lane & 15;
    const int lchk = lane >> 4;

#pragma unroll
    for (int ks = 0; ks < 16; ks++) {
        uint32_t a[4], bb[2][4];
        const int kc = ks * 2 + lchk;
        ldsm4(a, sb + SA + sw_off(wm * 16 + lrow, kc));
#pragma unroll
        for (int h = 0; h < 2; h++)
            ldsm4(bb[h], sb + SBo + sw_off(wn * 32 + h * 16 + lrow, kc));
#pragma unroll
        for (int nt = 0; nt < 4; nt++)
            mma16816(acc[nt], a, bb[nt >> 1][nt & 1], bb[nt >> 1][(nt & 1) + 2]);
    }

    __syncthreads();   // operands no longer needed; staging may overwrite

    // ---------------- epilogue: direct writes + transpose staging ----------------
    const float* xi2s = (const float*)(smem + SXI);
    const float* xj2s = (const float*)(smem + SXJ);
    float* sp = (float*)(smem + SP);
    float* sd = (float*)(smem + SD);
    const int g  = lane >> 2;
    const int tq = lane & 3;

    float2 xj2v[4];
#pragma unroll
    for (int nt = 0; nt < 4; nt++)
        xj2v[nt] = *(const float2*)(xj2s + wn * 32 + nt * 8 + tq * 2);

#pragma unroll
    for (int hf = 0; hf < 2; hf++) {
        const int il  = wm * 16 + g + hf * 8;
        const int gi  = i0 + il;
        const float xi2 = xi2s[il];
        const float Bv  = 1.0f - xi2;
        const float Bv2 = Bv * Bv;
#pragma unroll
        for (int nt = 0; nt < 4; nt++) {
            const int jl = wn * 32 + nt * 8 + tq * 2;
            const int gj = j0 + jl;
            float2 pr, dr;
#pragma unroll
            for (int e = 0; e < 2; e++) {
                const float dot = acc[nt][hf * 2 + e];
                const float xj2 = e ? xj2v[nt].y : xj2v[nt].x;
                const float A   = fmaf(-2.f, dot, 1.f + xj2);           // 1 - 2dot + xj2
                const float Dq  = fmaf(-2.f, dot, fmaf(xi2, xj2, 1.f)); // 1 - 2dot + xi2*xj2
                const float q   = fmaf(-(Bv + Bv), dot, A * xi2);       // A*xi2 - 2B*dot
                float num2 = fmaf(A, q, Bv2 * xj2);
                num2 = fmaxf(num2, 0.f);
                const float den = fmaxf(fabsf(Dq), 1e-15f);
                float rd, sq, l1, l2;
                asm("rcp.approx.f32 %0, %1;"  : "=f"(rd) : "f"(den));
                asm("sqrt.approx.f32 %0, %1;" : "=f"(sq) : "f"(num2));
                const float x = fminf(sq * rd, 1.0f - 1e-7f);
                float p = fmaf(-0.5f, x, 0.5f);            // sigmoid(-dist) == (1-x)/2 (c=1)
                asm("lg2.approx.f32 %0, %1;" : "=f"(l1) : "f"(1.f + x));
                asm("lg2.approx.f32 %0, %1;" : "=f"(l2) : "f"(1.f - x));
                float d = (l1 - l2) * 0.6931471805599453f; // 2*artanh(x)
                if (diag && gi == gj + e) { p = 0.f; d = 0.f; }
                if (e) { pr.y = p; dr.y = d; } else { pr.x = p; dr.x = d; }
                sp[il * PSTRIDE + jl + e] = p;             // transpose staging
                sd[il * PSTRIDE + jl + e] = d;
            }
            const size_t o = (size_t)gi * N_TOK + gj;
            if (!diag || gj >= gi) {
                *(float2*)(out + o)                         = pr;
                *(float2*)(out + o + (size_t)N_TOK * N_TOK) = dr;
            } else if (gj + 1 == gi) {   // straddling pair: upper elem only
                out[o + 1]                         = pr.y;
                out[o + 1 + (size_t)N_TOK * N_TOK] = dr.y;
            }
        }
    }

    // ---------------- mirrored block (coalesced) ----------------
    __syncthreads();
    if (!diag) {
#pragma unroll 4
        for (int k = 0; k < 16; k++) {
            int id = k * THREADS + tid;       // 0..4095
            int r  = id >> 6;                 // local j row 0..63
            int c  = id & 63;                 // local i col 0..63
            const size_t o = (size_t)(j0 + r) * N_TOK + (i0 + c);
            out[o]                         = sp[c * PSTRIDE + r];
            out[o + (size_t)N_TOK * N_TOK] = sd[c * PSTRIDE + r];
        }
    } else {
#pragma unroll 4
        for (int k = 0; k < 16; k++) {
            int id = k * THREADS + tid;
            int r  = id >> 6;
            int c  = id & 63;
            if (r > c) {                      // strictly below diagonal
                const size_t o = (size_t)(j0 + r) * N_TOK + (i0 + c);
                out[o]                         = sp[c * PSTRIDE + r];
                out[o + (size_t)N_TOK * N_TOK] = sd[c * PSTRIDE + r];
            }
        }
    }
}

// ===================== launch =====================
extern "C" void kernel_launch(void* const* d_in, const int* in_sizes, int n_in,
                              void* d_out, int out_size) {
    const float* emb = (const float*)d_in[0];
    float* out = (float*)d_out;

    cudaFuncSetAttribute(poincare_kernel, cudaFuncAttributeMaxDynamicSharedMemorySize, SMEM_TOTAL);

    prep_kernel<<<N_TOK / 8, 256>>>(emb);

    poincare_kernel<<<NTILES, THREADS, SMEM_TOTAL>>>(out);
}

// round 7
// speedup vs baseline: 1.4909x; 1.4909x over previous
#include <cuda_runtime.h>
#include <cuda_bf16.h>
#include <cstdint>

// ===================== problem constants =====================
#define N_TOK 8192
#define DIM   256          // K
#define BTI   128          // CTA tile rows (i)
#define BTJ   64           // CTA tile cols (j)
#define THREADS 256        // 8 warps: 4(i) x 2(j) warp grid, 32x32 per warp
#define NTILES 4160        // upper-tri rectangular tiles: sum_{ti<64} (128 - 2*ti)

__device__ __nv_bfloat16 g_emb[N_TOK * DIM];
__device__ float g_x2[N_TOK];

// ===================== helpers =====================
__device__ __forceinline__ uint32_t smem_u32(const void* p) {
    uint32_t a;
    asm("{ .reg .u64 t; cvta.to.shared.u64 t, %1; cvt.u32.u64 %0, t; }" : "=r"(a) : "l"(p));
    return a;
}

#define CP16(dst, src) \
    asm volatile("cp.async.cg.shared.global [%0], [%1], 16;" :: "r"(dst), "l"(src) : "memory")

__device__ __forceinline__ void ldsm4(uint32_t* r, uint32_t addr) {
    asm volatile("ldmatrix.sync.aligned.m8n8.x4.shared.b16 {%0,%1,%2,%3}, [%4];"
        : "=r"(r[0]), "=r"(r[1]), "=r"(r[2]), "=r"(r[3]) : "r"(addr));
}

__device__ __forceinline__ void mma16816(float* c, const uint32_t* a, uint32_t b0, uint32_t b1) {
    asm volatile("mma.sync.aligned.m16n8k16.row.col.f32.bf16.bf16.f32 "
        "{%0,%1,%2,%3}, {%4,%5,%6,%7}, {%8,%9}, {%0,%1,%2,%3};"
        : "+f"(c[0]), "+f"(c[1]), "+f"(c[2]), "+f"(c[3])
        : "r"(a[0]), "r"(a[1]), "r"(a[2]), "r"(a[3]), "r"(b0), "r"(b1));
}

// smem operand layout: row-major 512B rows (256 bf16), 16B chunks XOR-swizzled.
__device__ __forceinline__ uint32_t sw_off(int r, int kc) {
    return (uint32_t)r * 512u + (uint32_t)((kc ^ (r & 7)) << 4);
}

// ===================== prep: fp32 -> bf16 + exact fp32 row norms =====================
__global__ void prep_kernel(const float* __restrict__ emb) {
    const int row  = (blockIdx.x << 3) + (threadIdx.x >> 5);
    const int lane = threadIdx.x & 31;
    const float4* src = (const float4*)(emb + (size_t)row * DIM + lane * 8);
    float4 v0 = src[0], v1 = src[1];
    float s = v0.x * v0.x;
    s = fmaf(v0.y, v0.y, s); s = fmaf(v0.z, v0.z, s); s = fmaf(v0.w, v0.w, s);
    s = fmaf(v1.x, v1.x, s); s = fmaf(v1.y, v1.y, s);
    s = fmaf(v1.z, v1.z, s); s = fmaf(v1.w, v1.w, s);
#pragma unroll
    for (int o = 16; o; o >>= 1) s += __shfl_xor_sync(0xffffffffu, s, o);

    __nv_bfloat162 b0 = __floats2bfloat162_rn(v0.x, v0.y);
    __nv_bfloat162 b1 = __floats2bfloat162_rn(v0.z, v0.w);
    __nv_bfloat162 b2 = __floats2bfloat162_rn(v1.x, v1.y);
    __nv_bfloat162 b3 = __floats2bfloat162_rn(v1.z, v1.w);
    uint4 packed;
    packed.x = *(uint32_t*)&b0; packed.y = *(uint32_t*)&b1;
    packed.z = *(uint32_t*)&b2; packed.w = *(uint32_t*)&b3;
    *(uint4*)(g_emb + (size_t)row * DIM + lane * 8) = packed;
    if (lane == 0) g_x2[row] = s;
}

// ===================== smem layout (per CTA) =====================
// Phase 1: A tile (128 rows) 64KB @0, B tile (64 rows) 32KB @65536  -> 98304 B
// Phase 2 (reuses @0): packed (p,d) staging, 128 rows x 144 words = 73728 B
//   word addr of pair jl in row il: il*144 + (jl>>1)*4 + (jl&1)*2  (16B aligned)
// Norms beyond both: xi2 @98304 (512B), xj2 @98816 (256B). Total 99328 B.
#define SA   0u
#define SBo  65536u
#define SPD  0u
#define SXI  98304u
#define SXJ  98816u
#define SMEM_TOTAL 99328
#define SROW 144   // staging row stride in 4B words; 36 mod 8 == 4 -> conflict-free STS.128/LDS.128

__global__ void __launch_bounds__(THREADS, 2)
poincare_kernel(float* __restrict__ out) {
    extern __shared__ char smem[];
    uint32_t sb = smem_u32(smem);

    const int tid  = threadIdx.x;
    const int lane = tid & 31;
    const int w    = tid >> 5;
    const int wm   = w >> 1;   // warp row in 4x2 grid (i dim, 32 rows each)
    const int wn   = w & 1;    // warp col (j dim, 32 cols each)

    // ---- decode upper-tri rectangular tile: ti in [0,64), tjj in [2ti,128) ----
    const int t = blockIdx.x;
    int ti = (int)((129.0f - sqrtf(16641.0f - 4.0f * (float)t)) * 0.5f);
    while (ti > 0 && ti * (129 - ti) > t) ti--;
    while ((ti + 1) * (128 - ti) <= t) ti++;
    const int tjj = 2 * ti + (t - ti * (129 - ti));

    const int i0 = ti * BTI;
    const int j0 = tjj * BTJ;
    const bool band = (j0 < i0 + BTI);   // tile touches the diagonal band

    // stage row norms
    if (tid < 128)           ((float*)(smem + SXI))[tid]       = g_x2[i0 + tid];
    else if (tid < 192)      ((float*)(smem + SXJ))[tid - 128] = g_x2[j0 + tid - 128];

    // stage A (128 rows) and B (64 rows), full K=256
#pragma unroll
    for (int k = 0; k < 16; k++) {           // A: 4096 16B-chunks
        int id = k * THREADS + tid;
        int r = id >> 5, kc = id & 31;
        CP16(sb + SA + sw_off(r, kc), &g_emb[(size_t)(i0 + r) * DIM + kc * 8]);
    }
#pragma unroll
    for (int k = 0; k < 8; k++) {            // B: 2048 16B-chunks
        int id = k * THREADS + tid;
        int r = id >> 5, kc = id & 31;
        CP16(sb + SBo + sw_off(r, kc), &g_emb[(size_t)(j0 + r) * DIM + kc * 8]);
    }
    asm volatile("cp.async.commit_group;" ::: "memory");
    asm volatile("cp.async.wait_all;" ::: "memory");
    __syncthreads();

    // ---------------- MMA mainloop: 16 K-steps of k16 ----------------
    float acc[2][4][4];
#pragma unroll
    for (int mt = 0; mt < 2; mt++)
#pragma unroll
        for (int nt = 0; nt < 4; nt++)
#pragma unroll
            for (int e = 0; e < 4; e++) acc[mt][nt][e] = 0.f;

    const int lrow = lane & 15;
    const int lchk = lane >> 4;

#pragma unroll
    for (int ks = 0; ks < 16; ks++) {
        uint32_t a[2][4], bb[2][4];
        const int kc = ks * 2 + lchk;
#pragma unroll
        for (int mt = 0; mt < 2; mt++)
            ldsm4(a[mt], sb + SA + sw_off(wm * 32 + mt * 16 + lrow, kc));
#pragma unroll
        for (int h = 0; h < 2; h++)
            ldsm4(bb[h], sb + SBo + sw_off(wn * 32 + h * 16 + lrow, kc));
#pragma unroll
        for (int mt = 0; mt < 2; mt++)
#pragma unroll
            for (int nt = 0; nt < 4; nt++)
                mma16816(acc[mt][nt], a[mt], bb[nt >> 1][nt & 1], bb[nt >> 1][(nt & 1) + 2]);
    }

    __syncthreads();   // operands no longer needed; staging may overwrite

    // ---------------- epilogue: direct writes + packed transpose staging ----------------
    const float* xi2s = (const float*)(smem + SXI);
    const float* xj2s = (const float*)(smem + SXJ);
    float* spd = (float*)(smem + SPD);
    const int g  = lane >> 2;
    const int tq = lane & 3;

    float2 xj2v[4];
#pragma unroll
    for (int nt = 0; nt < 4; nt++)
        xj2v[nt] = *(const float2*)(xj2s + wn * 32 + nt * 8 + tq * 2);

    const int jbase = wn * 32 + tq * 2;     // jl for nt=0 (even)
    float* const outd = out + (size_t)N_TOK * N_TOK;

#pragma unroll
    for (int mt = 0; mt < 2; mt++) {
#pragma unroll
        for (int hf = 0; hf < 2; hf++) {
            const int il  = wm * 32 + mt * 16 + g + hf * 8;
            const int gi  = i0 + il;
            const float xi2 = xi2s[il];
            const float Bv  = 1.0f - xi2;
            const float Bv2 = Bv * Bv;
            float* srow  = spd + il * SROW + (jbase >> 1) * 4;  // 16B aligned
            float* orow  = out  + (size_t)gi * N_TOK + j0 + jbase;
            float* orowd = outd + (size_t)gi * N_TOK + j0 + jbase;
#pragma unroll
            for (int nt = 0; nt < 4; nt++) {
                const int gj = j0 + jbase + nt * 8;
                float2 pr, dr;
#pragma unroll
                for (int e = 0; e < 2; e++) {
                    const float dot = acc[mt][nt][hf * 2 + e];
                    const float xj2 = e ? xj2v[nt].y : xj2v[nt].x;
                    const float A   = fmaf(-2.f, dot, 1.f + xj2);           // 1 - 2dot + xj2
                    const float Dq  = fmaf(-2.f, dot, fmaf(xi2, xj2, 1.f)); // 1 - 2dot + xi2*xj2
                    const float q   = fmaf(-(Bv + Bv), dot, A * xi2);       // A*xi2 - 2B*dot
                    float num2 = fmaf(A, q, Bv2 * xj2);
                    num2 = fmaxf(num2, 0.f);
                    const float den = fmaxf(fabsf(Dq), 1e-15f);
                    float rd, sq, l1, l2;
                    asm("rcp.approx.f32 %0, %1;"  : "=f"(rd) : "f"(den));
                    asm("sqrt.approx.f32 %0, %1;" : "=f"(sq) : "f"(num2));
                    const float x = fminf(sq * rd, 1.0f - 1e-7f);
                    float p = fmaf(-0.5f, x, 0.5f);            // sigmoid(-dist) == (1-x)/2 (c=1)
                    asm("lg2.approx.f32 %0, %1;" : "=f"(l1) : "f"(1.f + x));
                    asm("lg2.approx.f32 %0, %1;" : "=f"(l2) : "f"(1.f - x));
                    float d = (l1 - l2) * 0.6931471805599453f; // 2*artanh(x)
                    if (gi == gj + e) { p = 0.f; d = 0.f; }    // diagonal mask
                    if (e) { pr.y = p; dr.y = d; } else { pr.x = p; dr.x = d; }
                }
                // packed staging: one conflict-free STS.128 (p0,d0,p1,d1)
                float4 pk; pk.x = pr.x; pk.y = dr.x; pk.z = pr.y; pk.w = dr.y;
                *(float4*)(srow + nt * 16) = pk;
                if (!band || gj >= gi) {
                    *(float2*)(orow  + nt * 8) = pr;
                    *(float2*)(orowd + nt * 8) = dr;
                } else if (gj + 1 == gi) {   // straddling pair: upper elem only
                    orow [nt * 8 + 1] = pr.y;
                    orowd[nt * 8 + 1] = dr.y;
                }
            }
        }
    }

    // ---------------- mirrored block (coalesced, LDS.128 reads) ----------------
    // Each thread reads one float4 = (p,d) for j-rows {2rr, 2rr+1} at column c.
    __syncthreads();
    if (!band) {
#pragma unroll 4
        for (int k = 0; k < 16; k++) {
            const int rr = (lane & 3) + ((k & 7) << 2);                 // 0..31
            const int c  = (lane >> 2) + (w << 3) + ((k >> 3) << 6);    // 0..127
            float4 v = *(const float4*)(spd + c * SROW + rr * 4);       // conflict-free
            const size_t o0 = (size_t)(j0 + 2 * rr) * N_TOK + (i0 + c);
            const size_t o1 = o0 + N_TOK;
            out[o0]  = v.x;  outd[o0] = v.y;
            out[o1]  = v.z;  outd[o1] = v.w;
        }
    } else {
#pragma unroll 4
        for (int k = 0; k < 16; k++) {
            const int rr = (lane & 3) + ((k & 7) << 2);
            const int c  = (lane >> 2) + (w << 3) + ((k >> 3) << 6);
            float4 v = *(const float4*)(spd + c * SROW + rr * 4);
            const int r0 = 2 * rr;
            const size_t o0 = (size_t)(j0 + r0) * N_TOK + (i0 + c);
            const size_t o1 = o0 + N_TOK;
            if (j0 + r0 > i0 + c)     { out[o0] = v.x; outd[o0] = v.y; }
            if (j0 + r0 + 1 > i0 + c) { out[o1] = v.z; outd[o1] = v.w; }
        }
    }
}

// ===================== launch =====================
extern "C" void kernel_launch(void* const* d_in, const int* in_sizes, int n_in,
                              void* d_out, int out_size) {
    const float* emb = (const float*)d_in[0];
    float* out = (float*)d_out;

    cudaFuncSetAttribute(poincare_kernel, cudaFuncAttributeMaxDynamicSharedMemorySize, SMEM_TOTAL);

    prep_kernel<<<N_TOK / 8, 256>>>(emb);

    poincare_kernel<<<NTILES, THREADS, SMEM_TOTAL>>>(out);
}

// round 8
// speedup vs baseline: 1.6347x; 1.0964x over previous
#include <cuda_runtime.h>
#include <cuda_bf16.h>
#include <cstdint>

// ===================== problem constants =====================
#define N_TOK 8192
#define DIM   256          // K
#define BTI   128          // CTA tile rows (i)
#define BTJ   64           // CTA tile cols (j)
#define THREADS 256        // 8 warps: 4(i) x 2(j) warp grid, 32x32 per warp
#define NTILES 4160        // upper-tri rectangular tiles: sum_{ti<64} (128 - 2*ti)

__device__ __nv_bfloat16 g_emb[N_TOK * DIM];
__device__ float g_x2[N_TOK];

// ===================== helpers =====================
__device__ __forceinline__ uint32_t smem_u32(const void* p) {
    uint32_t a;
    asm("{ .reg .u64 t; cvta.to.shared.u64 t, %1; cvt.u32.u64 %0, t; }" : "=r"(a) : "l"(p));
    return a;
}

#define CP16(dst, src) \
    asm volatile("cp.async.cg.shared.global [%0], [%1], 16;" :: "r"(dst), "l"(src) : "memory")

__device__ __forceinline__ void ldsm4(uint32_t* r, uint32_t addr) {
    asm volatile("ldmatrix.sync.aligned.m8n8.x4.shared.b16 {%0,%1,%2,%3}, [%4];"
        : "=r"(r[0]), "=r"(r[1]), "=r"(r[2]), "=r"(r[3]) : "r"(addr));
}

__device__ __forceinline__ void mma16816(float* c, const uint32_t* a, uint32_t b0, uint32_t b1) {
    asm volatile("mma.sync.aligned.m16n8k16.row.col.f32.bf16.bf16.f32 "
        "{%0,%1,%2,%3}, {%4,%5,%6,%7}, {%8,%9}, {%0,%1,%2,%3};"
        : "+f"(c[0]), "+f"(c[1]), "+f"(c[2]), "+f"(c[3])
        : "r"(a[0]), "r"(a[1]), "r"(a[2]), "r"(a[3]), "r"(b0), "r"(b1));
}

// smem operand layout: row-major 512B rows (256 bf16), 16B chunks XOR-swizzled.
__device__ __forceinline__ uint32_t sw_off(int r, int kc) {
    return (uint32_t)r * 512u + (uint32_t)((kc ^ (r & 7)) << 4);
}

// ===================== prep: fp32 -> bf16 + exact fp32 row norms =====================
__global__ void prep_kernel(const float* __restrict__ emb) {
    const int row  = (blockIdx.x << 3) + (threadIdx.x >> 5);
    const int lane = threadIdx.x & 31;
    const float4* src = (const float4*)(emb + (size_t)row * DIM + lane * 8);
    float4 v0 = src[0], v1 = src[1];
    float s = v0.x * v0.x;
    s = fmaf(v0.y, v0.y, s); s = fmaf(v0.z, v0.z, s); s = fmaf(v0.w, v0.w, s);
    s = fmaf(v1.x, v1.x, s); s = fmaf(v1.y, v1.y, s);
    s = fmaf(v1.z, v1.z, s); s = fmaf(v1.w, v1.w, s);
#pragma unroll
    for (int o = 16; o; o >>= 1) s += __shfl_xor_sync(0xffffffffu, s, o);

    __nv_bfloat162 b0 = __floats2bfloat162_rn(v0.x, v0.y);
    __nv_bfloat162 b1 = __floats2bfloat162_rn(v0.z, v0.w);
    __nv_bfloat162 b2 = __floats2bfloat162_rn(v1.x, v1.y);
    __nv_bfloat162 b3 = __floats2bfloat162_rn(v1.z, v1.w);
    uint4 packed;
    packed.x = *(uint32_t*)&b0; packed.y = *(uint32_t*)&b1;
    packed.z = *(uint32_t*)&b2; packed.w = *(uint32_t*)&b3;
    *(uint4*)(g_emb + (size_t)row * DIM + lane * 8) = packed;
    if (lane == 0) g_x2[row] = s;
}

// ===================== smem layout (per CTA) =====================
// Phase 1: A tile (128 rows) 64KB @0, B tile (64 rows) 32KB @65536  -> 98304 B
// Phase 2 (reuses @0): probs staging 128x69 fl @0 (35328B), dists @35328 -> 70656
// Norms beyond both: xi2 @98304 (512B), xj2 @98816 (256B). Total 99328 B.
#define SA   0u
#define SBo  65536u
#define SP   0u
#define SD   35328u
#define SXI  98304u
#define SXJ  98816u
#define SMEM_TOTAL 99328
#define PSTRIDE 69   // odd -> conflict-free scattered STS + column LDS

__global__ void __launch_bounds__(THREADS, 2)
poincare_kernel(float* __restrict__ out) {
    extern __shared__ char smem[];
    uint32_t sb = smem_u32(smem);

    const int tid  = threadIdx.x;
    const int lane = tid & 31;
    const int w    = tid >> 5;
    const int wm   = w >> 1;   // warp row in 4x2 grid (i dim, 32 rows each)
    const int wn   = w & 1;    // warp col (j dim, 32 cols each)

    // ---- decode upper-tri rectangular tile: ti in [0,64), tjj in [2ti,128) ----
    const int t = blockIdx.x;
    int ti = (int)((129.0f - sqrtf(16641.0f - 4.0f * (float)t)) * 0.5f);
    while (ti > 0 && ti * (129 - ti) > t) ti--;
    while ((ti + 1) * (128 - ti) <= t) ti++;
    const int tjj = 2 * ti + (t - ti * (129 - ti));

    const int i0 = ti * BTI;
    const int j0 = tjj * BTJ;
    const bool band = (j0 < i0 + BTI);   // tile touches the diagonal band

    // stage row norms
    if (tid < 128)           ((float*)(smem + SXI))[tid]       = g_x2[i0 + tid];
    else if (tid < 192)      ((float*)(smem + SXJ))[tid - 128] = g_x2[j0 + tid - 128];

    // ---- K-split double-buffered loads: group0 = kc 0..15, group1 = kc 16..31 ----
    // A half: 128 rows x 16 chunks = 2048; B half: 64 x 16 = 1024.
#pragma unroll
    for (int k = 0; k < 8; k++) {            // A, K-half 0
        int id = k * THREADS + tid;
        int r = id >> 4, kc = id & 15;
        CP16(sb + SA + sw_off(r, kc), &g_emb[(size_t)(i0 + r) * DIM + kc * 8]);
    }
#pragma unroll
    for (int k = 0; k < 4; k++) {            // B, K-half 0
        int id = k * THREADS + tid;
        int r = id >> 4, kc = id & 15;
        CP16(sb + SBo + sw_off(r, kc), &g_emb[(size_t)(j0 + r) * DIM + kc * 8]);
    }
    asm volatile("cp.async.commit_group;" ::: "memory");
#pragma unroll
    for (int k = 0; k < 8; k++) {            // A, K-half 1
        int id = k * THREADS + tid;
        int r = id >> 4, kc = 16 + (id & 15);
        CP16(sb + SA + sw_off(r, kc), &g_emb[(size_t)(i0 + r) * DIM + kc * 8]);
    }
#pragma unroll
    for (int k = 0; k < 4; k++) {            // B, K-half 1
        int id = k * THREADS + tid;
        int r = id >> 4, kc = 16 + (id & 15);
        CP16(sb + SBo + sw_off(r, kc), &g_emb[(size_t)(j0 + r) * DIM + kc * 8]);
    }
    asm volatile("cp.async.commit_group;" ::: "memory");

    // ---------------- MMA mainloop: 2 halves of 8 K-steps ----------------
    float acc[2][4][4];
#pragma unroll
    for (int mt = 0; mt < 2; mt++)
#pragma unroll
        for (int nt = 0; nt < 4; nt++)
#pragma unroll
            for (int e = 0; e < 4; e++) acc[mt][nt][e] = 0.f;

    const int lrow = lane & 15;
    const int lchk = lane >> 4;

    asm volatile("cp.async.wait_group 1;" ::: "memory");   // K-half 0 resident
    __syncthreads();

#pragma unroll
    for (int ks = 0; ks < 8; ks++) {
        uint32_t a[2][4], bb[2][4];
        const int kc = ks * 2 + lchk;
#pragma unroll
        for (int mt = 0; mt < 2; mt++)
            ldsm4(a[mt], sb + SA + sw_off(wm * 32 + mt * 16 + lrow, kc));
#pragma unroll
        for (int h = 0; h < 2; h++)
            ldsm4(bb[h], sb + SBo + sw_off(wn * 32 + h * 16 + lrow, kc));
#pragma unroll
        for (int mt = 0; mt < 2; mt++)
#pragma unroll
            for (int nt = 0; nt < 4; nt++)
                mma16816(acc[mt][nt], a[mt], bb[nt >> 1][nt & 1], bb[nt >> 1][(nt & 1) + 2]);
    }

    asm volatile("cp.async.wait_group 0;" ::: "memory");   // K-half 1 resident
    __syncthreads();

#pragma unroll
    for (int ks = 8; ks < 16; ks++) {
        uint32_t a[2][4], bb[2][4];
        const int kc = ks * 2 + lchk;
#pragma unroll
        for (int mt = 0; mt < 2; mt++)
            ldsm4(a[mt], sb + SA + sw_off(wm * 32 + mt * 16 + lrow, kc));
#pragma unroll
        for (int h = 0; h < 2; h++)
            ldsm4(bb[h], sb + SBo + sw_off(wn * 32 + h * 16 + lrow, kc));
#pragma unroll
        for (int mt = 0; mt < 2; mt++)
#pragma unroll
            for (int nt = 0; nt < 4; nt++)
                mma16816(acc[mt][nt], a[mt], bb[nt >> 1][nt & 1], bb[nt >> 1][(nt & 1) + 2]);
    }

    __syncthreads();   // operands no longer needed; staging may overwrite

    // ---------------- epilogue: direct writes + transpose staging ----------------
    const float* xi2s = (const float*)(smem + SXI);
    const float* xj2s = (const float*)(smem + SXJ);
    float* sp = (float*)(smem + SP);
    float* sd = (float*)(smem + SD);
    const int g  = lane >> 2;
    const int tq = lane & 3;

    float2 xj2v[4], onej[4];
#pragma unroll
    for (int nt = 0; nt < 4; nt++) {
        xj2v[nt] = *(const float2*)(xj2s + wn * 32 + nt * 8 + tq * 2);
        onej[nt].x = 1.f + xj2v[nt].x;
        onej[nt].y = 1.f + xj2v[nt].y;
    }

#pragma unroll
    for (int mt = 0; mt < 2; mt++) {
#pragma unroll
        for (int hf = 0; hf < 2; hf++) {
            const int il  = wm * 32 + mt * 16 + g + hf * 8;
            const int gi  = i0 + il;
            const float xi2 = xi2s[il];
            const float Bv  = 1.0f - xi2;
            const float Bv2 = Bv * Bv;
#pragma unroll
            for (int nt = 0; nt < 4; nt++) {
                const int jl = wn * 32 + nt * 8 + tq * 2;
                const int gj = j0 + jl;
                float2 pr, dr;
#pragma unroll
                for (int e = 0; e < 2; e++) {
                    const float dot = acc[mt][nt][hf * 2 + e];
                    const float xj2 = e ? xj2v[nt].y : xj2v[nt].x;
                    const float A   = fmaf(-2.f, dot, e ? onej[nt].y : onej[nt].x);
                    const float Dq  = fmaf(-2.f, dot, fmaf(xi2, xj2, 1.f)); // 1 - 2dot + xi2*xj2
                    const float q   = fmaf(-(Bv + Bv), dot, A * xi2);       // A*xi2 - 2B*dot
                    float num2 = fmaf(A, q, Bv2 * xj2);
                    num2 = fmaxf(num2, 0.f);
                    const float den = fmaxf(fabsf(Dq), 1e-15f);
                    float rd, sq, l1, l2;
                    asm("rcp.approx.f32 %0, %1;"  : "=f"(rd) : "f"(den));
                    asm("sqrt.approx.f32 %0, %1;" : "=f"(sq) : "f"(num2));
                    const float x = fminf(sq * rd, 1.0f - 1e-7f);
                    float p = fmaf(-0.5f, x, 0.5f);            // sigmoid(-dist) == (1-x)/2 (c=1)
                    asm("lg2.approx.f32 %0, %1;" : "=f"(l1) : "f"(1.f + x));
                    asm("lg2.approx.f32 %0, %1;" : "=f"(l2) : "f"(1.f - x));
                    float d = (l1 - l2) * 0.6931471805599453f; // 2*artanh(x)
                    if (gi == gj + e) { p = 0.f; d = 0.f; }    // diagonal mask
                    if (e) { pr.y = p; dr.y = d; } else { pr.x = p; dr.x = d; }
                    sp[il * PSTRIDE + jl + e] = p;             // transpose staging
                    sd[il * PSTRIDE + jl + e] = d;
                }
                const size_t o = (size_t)gi * N_TOK + gj;
                if (!band || gj >= gi) {
                    *(float2*)(out + o)                         = pr;
                    *(float2*)(out + o + (size_t)N_TOK * N_TOK) = dr;
                } else if (gj + 1 == gi) {   // straddling pair: upper elem only
                    out[o + 1]                         = pr.y;
                    out[o + 1 + (size_t)N_TOK * N_TOK] = dr.y;
                }
            }
        }
    }

    // ---------------- mirrored block (coalesced) ----------------
    __syncthreads();
    if (!band) {
#pragma unroll 4
        for (int k = 0; k < 32; k++) {
            int id = k * THREADS + tid;       // 0..8191
            int r  = id >> 7;                 // local j row 0..63
            int c  = id & 127;                // local i col 0..127
            const size_t o = (size_t)(j0 + r) * N_TOK + (i0 + c);
            out[o]                         = sp[c * PSTRIDE + r];
            out[o + (size_t)N_TOK * N_TOK] = sd[c * PSTRIDE + r];
        }
    } else {
#pragma unroll 4
        for (int k = 0; k < 32; k++) {
            int id = k * THREADS + tid;
            int r  = id >> 7;
            int c  = id & 127;
            if (j0 + r > i0 + c) {            // strictly below diagonal
                const size_t o = (size_t)(j0 + r) * N_TOK + (i0 + c);
                out[o]                         = sp[c * PSTRIDE + r];
                out[o + (size_t)N_TOK * N_TOK] = sd[c * PSTRIDE + r];
            }
        }
    }
}

// ===================== launch =====================
extern "C" void kernel_launch(void* const* d_in, const int* in_sizes, int n_in,
                              void* d_out, int out_size) {
    const float* emb = (const float*)d_in[0];
    float* out = (float*)d_out;

    cudaFuncSetAttribute(poincare_kernel, cudaFuncAttributeMaxDynamicSharedMemorySize, SMEM_TOTAL);

    prep_kernel<<<N_TOK / 8, 256>>>(emb);

    poincare_kernel<<<NTILES, THREADS, SMEM_TOTAL>>>(out);
}

// round 9
// speedup vs baseline: 1.6384x; 1.0023x over previous
#include <cuda_runtime.h>
#include <cuda_bf16.h>
#include <cstdint>

// ===================== problem constants =====================
#define N_TOK 8192
#define DIM   256          // K
#define BTI   128          // CTA tile rows (i)
#define BTJ   64           // CTA tile cols (j)
#define THREADS 256        // 8 warps: 4(i) x 2(j) warp grid, 32x32 per warp
#define NTILES 4160        // upper-tri rectangular tiles: sum_{ti<64} (128 - 2*ti)

__device__ __nv_bfloat16 g_emb[N_TOK * DIM];
__device__ float g_x2[N_TOK];

// ===================== helpers =====================
__device__ __forceinline__ uint32_t smem_u32(const void* p) {
    uint32_t a;
    asm("{ .reg .u64 t; cvta.to.shared.u64 t, %1; cvt.u32.u64 %0, t; }" : "=r"(a) : "l"(p));
    return a;
}

#define CP16(dst, src) \
    asm volatile("cp.async.cg.shared.global [%0], [%1], 16;" :: "r"(dst), "l"(src) : "memory")

__device__ __forceinline__ void ldsm4(uint32_t* r, uint32_t addr) {
    asm volatile("ldmatrix.sync.aligned.m8n8.x4.shared.b16 {%0,%1,%2,%3}, [%4];"
        : "=r"(r[0]), "=r"(r[1]), "=r"(r[2]), "=r"(r[3]) : "r"(addr));
}

__device__ __forceinline__ void mma16816(float* c, const uint32_t* a, uint32_t b0, uint32_t b1) {
    asm volatile("mma.sync.aligned.m16n8k16.row.col.f32.bf16.bf16.f32 "
        "{%0,%1,%2,%3}, {%4,%5,%6,%7}, {%8,%9}, {%0,%1,%2,%3};"
        : "+f"(c[0]), "+f"(c[1]), "+f"(c[2]), "+f"(c[3])
        : "r"(a[0]), "r"(a[1]), "r"(a[2]), "r"(a[3]), "r"(b0), "r"(b1));
}

// smem operand layout: row-major 512B rows (256 bf16), 16B chunks XOR-swizzled.
__device__ __forceinline__ uint32_t sw_off(int r, int kc) {
    return (uint32_t)r * 512u + (uint32_t)((kc ^ (r & 7)) << 4);
}

// ===================== prep: fp32 -> bf16 + exact fp32 row norms =====================
__global__ void prep_kernel(const float* __restrict__ emb) {
    const int row  = (blockIdx.x << 3) + (threadIdx.x >> 5);
    const int lane = threadIdx.x & 31;
    const float4* src = (const float4*)(emb + (size_t)row * DIM + lane * 8);
    float4 v0 = src[0], v1 = src[1];
    float s = v0.x * v0.x;
    s = fmaf(v0.y, v0.y, s); s = fmaf(v0.z, v0.z, s); s = fmaf(v0.w, v0.w, s);
    s = fmaf(v1.x, v1.x, s); s = fmaf(v1.y, v1.y, s);
    s = fmaf(v1.z, v1.z, s); s = fmaf(v1.w, v1.w, s);
#pragma unroll
    for (int o = 16; o; o >>= 1) s += __shfl_xor_sync(0xffffffffu, s, o);

    __nv_bfloat162 b0 = __floats2bfloat162_rn(v0.x, v0.y);
    __nv_bfloat162 b1 = __floats2bfloat162_rn(v0.z, v0.w);
    __nv_bfloat162 b2 = __floats2bfloat162_rn(v1.x, v1.y);
    __nv_bfloat162 b3 = __floats2bfloat162_rn(v1.z, v1.w);
    uint4 packed;
    packed.x = *(uint32_t*)&b0; packed.y = *(uint32_t*)&b1;
    packed.z = *(uint32_t*)&b2; packed.w = *(uint32_t*)&b3;
    *(uint4*)(g_emb + (size_t)row * DIM + lane * 8) = packed;
    if (lane == 0) g_x2[row] = s;
}

// ===================== smem layout (per CTA) =====================
// Phase 1: A tile (128 rows) 64KB @0, B tile (64 rows) 32KB @65536  -> 98304 B
// Phase 2 (reuses @0): transposed x staging xT[j][i], 64 rows x 132 words = 33792 B
//   STS banks: 2*tq*132 mod 32 = {0,8,16,24} + g(0..7) -> 32 distinct, conflict-free
// Norms beyond both: xi2 @98304 (512B), xj2 @98816 (256B). Total 99328 B.
#define SA   0u
#define SBo  65536u
#define SX   0u
#define SXI  98304u
#define SXJ  98816u
#define SMEM_TOTAL 99328
#define XROW 132   // xT row stride in words

__global__ void __launch_bounds__(THREADS, 2)
poincare_kernel(float* __restrict__ out) {
    extern __shared__ char smem[];
    uint32_t sb = smem_u32(smem);

    const int tid  = threadIdx.x;
    const int lane = tid & 31;
    const int w    = tid >> 5;
    const int wm   = w >> 1;   // warp row in 4x2 grid (i dim, 32 rows each)
    const int wn   = w & 1;    // warp col (j dim, 32 cols each)

    // ---- decode upper-tri rectangular tile: ti in [0,64), tjj in [2ti,128) ----
    const int t = blockIdx.x;
    int ti = (int)((129.0f - sqrtf(16641.0f - 4.0f * (float)t)) * 0.5f);
    while (ti > 0 && ti * (129 - ti) > t) ti--;
    while ((ti + 1) * (128 - ti) <= t) ti++;
    const int tjj = 2 * ti + (t - ti * (129 - ti));

    const int i0 = ti * BTI;
    const int j0 = tjj * BTJ;
    const bool band = (j0 < i0 + BTI);   // tile touches the diagonal band

    // stage row norms
    if (tid < 128)           ((float*)(smem + SXI))[tid]       = g_x2[i0 + tid];
    else if (tid < 192)      ((float*)(smem + SXJ))[tid - 128] = g_x2[j0 + tid - 128];

    // ---- K-split loads: group0 = kc 0..15, group1 = kc 16..31 ----
#pragma unroll
    for (int k = 0; k < 8; k++) {            // A, K-half 0
        int id = k * THREADS + tid;
        int r = id >> 4, kc = id & 15;
        CP16(sb + SA + sw_off(r, kc), &g_emb[(size_t)(i0 + r) * DIM + kc * 8]);
    }
#pragma unroll
    for (int k = 0; k < 4; k++) {            // B, K-half 0
        int id = k * THREADS + tid;
        int r = id >> 4, kc = id & 15;
        CP16(sb + SBo + sw_off(r, kc), &g_emb[(size_t)(j0 + r) * DIM + kc * 8]);
    }
    asm volatile("cp.async.commit_group;" ::: "memory");
#pragma unroll
    for (int k = 0; k < 8; k++) {            // A, K-half 1
        int id = k * THREADS + tid;
        int r = id >> 4, kc = 16 + (id & 15);
        CP16(sb + SA + sw_off(r, kc), &g_emb[(size_t)(i0 + r) * DIM + kc * 8]);
    }
#pragma unroll
    for (int k = 0; k < 4; k++) {            // B, K-half 1
        int id = k * THREADS + tid;
        int r = id >> 4, kc = 16 + (id & 15);
        CP16(sb + SBo + sw_off(r, kc), &g_emb[(size_t)(j0 + r) * DIM + kc * 8]);
    }
    asm volatile("cp.async.commit_group;" ::: "memory");

    // ---------------- MMA mainloop: 2 halves of 8 K-steps ----------------
    float acc[2][4][4];
#pragma unroll
    for (int mt = 0; mt < 2; mt++)
#pragma unroll
        for (int nt = 0; nt < 4; nt++)
#pragma unroll
            for (int e = 0; e < 4; e++) acc[mt][nt][e] = 0.f;

    const int lrow = lane & 15;
    const int lchk = lane >> 4;

    asm volatile("cp.async.wait_group 1;" ::: "memory");
    __syncthreads();

#pragma unroll
    for (int ks = 0; ks < 8; ks++) {
        uint32_t a[2][4], bb[2][4];
        const int kc = ks * 2 + lchk;
#pragma unroll
        for (int mt = 0; mt < 2; mt++)
            ldsm4(a[mt], sb + SA + sw_off(wm * 32 + mt * 16 + lrow, kc));
#pragma unroll
        for (int h = 0; h < 2; h++)
            ldsm4(bb[h], sb + SBo + sw_off(wn * 32 + h * 16 + lrow, kc));
#pragma unroll
        for (int mt = 0; mt < 2; mt++)
#pragma unroll
            for (int nt = 0; nt < 4; nt++)
                mma16816(acc[mt][nt], a[mt], bb[nt >> 1][nt & 1], bb[nt >> 1][(nt & 1) + 2]);
    }

    asm volatile("cp.async.wait_group 0;" ::: "memory");
    __syncthreads();

#pragma unroll
    for (int ks = 8; ks < 16; ks++) {
        uint32_t a[2][4], bb[2][4];
        const int kc = ks * 2 + lchk;
#pragma unroll
        for (int mt = 0; mt < 2; mt++)
            ldsm4(a[mt], sb + SA + sw_off(wm * 32 + mt * 16 + lrow, kc));
#pragma unroll
        for (int h = 0; h < 2; h++)
            ldsm4(bb[h], sb + SBo + sw_off(wn * 32 + h * 16 + lrow, kc));
#pragma unroll
        for (int mt = 0; mt < 2; mt++)
#pragma unroll
            for (int nt = 0; nt < 4; nt++)
                mma16816(acc[mt][nt], a[mt], bb[nt >> 1][nt & 1], bb[nt >> 1][(nt & 1) + 2]);
    }

    __syncthreads();   // operands no longer needed; staging may overwrite

    // ---------------- epilogue: direct writes + transposed x staging ----------------
    const float* xi2s = (const float*)(smem + SXI);
    const float* xj2s = (const float*)(smem + SXJ);
    float* sx = (float*)(smem + SX);
    const int g  = lane >> 2;
    const int tq = lane & 3;

    float2 xj2v[4], onej[4];
#pragma unroll
    for (int nt = 0; nt < 4; nt++) {
        xj2v[nt] = *(const float2*)(xj2s + wn * 32 + nt * 8 + tq * 2);
        onej[nt].x = 1.f + xj2v[nt].x;
        onej[nt].y = 1.f + xj2v[nt].y;
    }

    const int jbase = wn * 32 + tq * 2;
    float* const outd = out + (size_t)N_TOK * N_TOK;

#pragma unroll
    for (int mt = 0; mt < 2; mt++) {
#pragma unroll
        for (int hf = 0; hf < 2; hf++) {
            const int il  = wm * 32 + mt * 16 + g + hf * 8;
            const int gi  = i0 + il;
            const float xi2 = xi2s[il];
            const float Bv  = 1.0f - xi2;
            const float Bv2 = Bv * Bv;
            float* sxi = sx + jbase * XROW + il;   // + nt*8*XROW + e*XROW
#pragma unroll
            for (int nt = 0; nt < 4; nt++) {
                const int jl = jbase + nt * 8;
                const int gj = j0 + jl;
                float2 pr, dr;
#pragma unroll
                for (int e = 0; e < 2; e++) {
                    const float dot = acc[mt][nt][hf * 2 + e];
                    const float xj2 = e ? xj2v[nt].y : xj2v[nt].x;
                    const float A   = fmaf(-2.f, dot, e ? onej[nt].y : onej[nt].x);
                    const float Dq  = fmaf(-2.f, dot, fmaf(xi2, xj2, 1.f)); // 1 - 2dot + xi2*xj2
                    const float q   = fmaf(-(Bv + Bv), dot, A * xi2);       // A*xi2 - 2B*dot
                    float num2 = fmaf(A, q, Bv2 * xj2);
                    num2 = fmaxf(num2, 0.f);
                    const float den = fmaxf(fabsf(Dq), 1e-15f);
                    float rd, sq, l1, l2;
                    asm("rcp.approx.f32 %0, %1;"  : "=f"(rd) : "f"(den));
                    asm("sqrt.approx.f32 %0, %1;" : "=f"(sq) : "f"(num2));
                    const float x = fminf(sq * rd, 1.0f - 1e-7f);
                    sx[(jl + e) * XROW + il] = x;              // transposed staging
                    float p = fmaf(-0.5f, x, 0.5f);            // sigmoid(-dist) == (1-x)/2 (c=1)
                    asm("lg2.approx.f32 %0, %1;" : "=f"(l1) : "f"(1.f + x));
                    asm("lg2.approx.f32 %0, %1;" : "=f"(l2) : "f"(1.f - x));
                    float d = (l1 - l2) * 0.6931471805599453f; // 2*artanh(x)
                    if (gi == gj + e) { p = 0.f; d = 0.f; }    // diagonal mask
                    if (e) { pr.y = p; dr.y = d; } else { pr.x = p; dr.x = d; }
                }
                const size_t o = (size_t)gi * N_TOK + gj;
                if (!band || gj >= gi) {
                    *(float2*)(out + o)                         = pr;
                    *(float2*)(outd + o)                        = dr;
                } else if (gj + 1 == gi) {   // straddling pair: upper elem only
                    out [o + 1] = pr.y;
                    outd[o + 1] = dr.y;
                }
            }
            (void)sxi;
        }
    }

    // ---------------- mirrored block: recompute (p,d) from staged x ----------------
    // Each thread handles a float2 of adjacent columns c,c+1 in mirror row j0+r.
    __syncthreads();
#pragma unroll 4
    for (int k = 0; k < 16; k++) {
        const int id = k * THREADS + tid;     // 0..4095 pair ids
        const int r  = id >> 6;               // local j row 0..63
        const int c  = (id & 63) * 2;         // local i col, even
        float2 xv = *(const float2*)(sx + r * XROW + c);   // LDS.64 conflict-free

        float l1a, l2a, l1b, l2b;
        asm("lg2.approx.f32 %0, %1;" : "=f"(l1a) : "f"(1.f + xv.x));
        asm("lg2.approx.f32 %0, %1;" : "=f"(l2a) : "f"(1.f - xv.x));
        asm("lg2.approx.f32 %0, %1;" : "=f"(l1b) : "f"(1.f + xv.y));
        asm("lg2.approx.f32 %0, %1;" : "=f"(l2b) : "f"(1.f - xv.y));
        float2 pr, dr;
        pr.x = fmaf(-0.5f, xv.x, 0.5f);
        pr.y = fmaf(-0.5f, xv.y, 0.5f);
        dr.x = (l1a - l2a) * 0.6931471805599453f;
        dr.y = (l1b - l2b) * 0.6931471805599453f;

        const size_t o = (size_t)(j0 + r) * N_TOK + (i0 + c);
        if (!band) {
            *(float2*)(out  + o) = pr;
            *(float2*)(outd + o) = dr;
        } else {
            const int jr = j0 + r, ic = i0 + c;
            if (jr > ic)     { out[o]     = pr.x; outd[o]     = dr.x; }
            if (jr > ic + 1) { out[o + 1] = pr.y; outd[o + 1] = dr.y; }
        }
    }
}

// ===================== launch =====================
extern "C" void kernel_launch(void* const* d_in, const int* in_sizes, int n_in,
                              void* d_out, int out_size) {
    const float* emb = (const float*)d_in[0];
    float* out = (float*)d_out;

    cudaFuncSetAttribute(poincare_kernel, cudaFuncAttributeMaxDynamicSharedMemorySize, SMEM_TOTAL);

    prep_kernel<<<N_TOK / 8, 256>>>(emb);

    poincare_kernel<<<NTILES, THREADS, SMEM_TOTAL>>>(out);
}